// round 3
// baseline (speedup 1.0000x reference)
#include <cuda_runtime.h>
#include <math.h>

#define N_ADDR 150000
#define N_TX   200000
#define HID    32
#define E_AT   1000000
#define E_TA   1000000
#define E_AA   500000
#define SLOPE  0.2f
#define TB     256
#define SCAN_T 1024

// ---------------------------------------------------------------------------
// Scratch (device global — no runtime allocation)
// ---------------------------------------------------------------------------
struct __align__(128) Scratch {
    float ha [N_ADDR * HID];
    float ht [N_TX   * HID];
    float A  [N_ADDR * HID];
    float otx[N_TX   * HID];
    float oa1[N_ADDR * HID];
    float oa2[N_ADDR * HID];
    float as_at[N_ADDR * 4];
    float ad_at[N_TX   * 4];
    float as_ta[N_TX   * 4];
    float ad_ta[N_ADDR * 4];
    float as_aa[N_ADDR * 4];
    float ad_aa[N_ADDR * 4];
    float sem[64];
    float attn[2];
    // CSR (by destination) for the three edge types
    int cnt_at[N_TX];   int cur_at[N_TX];   int rs_at[N_TX];   int col_at[E_AT];
    int cnt_ta[N_ADDR]; int cur_ta[N_ADDR]; int rs_ta[N_ADDR]; int col_ta[E_TA];
    int cnt_aa[N_ADDR]; int cur_aa[N_ADDR]; int rs_aa[N_ADDR]; int col_aa[E_AA];
    int bsums[512];
};
__device__ Scratch g_scr;

__device__ __forceinline__ float leaky(float v) { return v >= 0.f ? v : SLOPE * v; }

// ---------------------------------------------------------------------------
// CSR build
// ---------------------------------------------------------------------------
__global__ void hist_kernel(const int* __restrict__ dst, int E, int* __restrict__ cnt)
{
    int e = blockIdx.x * blockDim.x + threadIdx.x;
    if (e < E) atomicAdd(&cnt[dst[e]], 1);
}

__global__ void scan_reduce_kernel(const int* __restrict__ cnt, int n, int* __restrict__ bsums)
{
    __shared__ int sd[SCAN_T];
    int tid = threadIdx.x;
    int i = blockIdx.x * SCAN_T + tid;
    sd[tid] = (i < n) ? cnt[i] : 0;
    __syncthreads();
#pragma unroll
    for (int off = SCAN_T / 2; off > 0; off >>= 1) {
        if (tid < off) sd[tid] += sd[tid + off];
        __syncthreads();
    }
    if (tid == 0) bsums[blockIdx.x] = sd[0];
}

__global__ void scan_bsums_kernel(int* __restrict__ bsums, int nb)
{
    __shared__ int sd[512];
    int tid = threadIdx.x;
    sd[tid] = (tid < nb) ? bsums[tid] : 0;
    __syncthreads();
    if (tid == 0) {
        int run = 0;
        for (int i = 0; i < nb; i++) { int t = sd[i]; sd[i] = run; run += t; }
    }
    __syncthreads();
    if (tid < nb) bsums[tid] = sd[tid];
}

__global__ void scan_apply_kernel(const int* __restrict__ cnt, int* __restrict__ rs,
                                  const int* __restrict__ bsums, int n)
{
    __shared__ int sd[SCAN_T];
    int tid = threadIdx.x;
    int i = blockIdx.x * SCAN_T + tid;
    int v = (i < n) ? cnt[i] : 0;
    sd[tid] = v;
    __syncthreads();
#pragma unroll
    for (int off = 1; off < SCAN_T; off <<= 1) {
        int t = (tid >= off) ? sd[tid - off] : 0;
        __syncthreads();
        sd[tid] += t;
        __syncthreads();
    }
    if (i < n) rs[i] = sd[tid] - v + bsums[blockIdx.x];
}

__global__ void fill_kernel(const int* __restrict__ src, const int* __restrict__ dst, int E,
                            const int* __restrict__ rs, int* __restrict__ cur,
                            int* __restrict__ col)
{
    int e = blockIdx.x * blockDim.x + threadIdx.x;
    if (e >= E) return;
    int d = dst[e];
    int pos = rs[d] + atomicAdd(&cur[d], 1);
    col[pos] = src[e];
}

// ---------------------------------------------------------------------------
// Projection: h = (relu?)x @ W + b; fused alpha dot-products (up to 4)
// ---------------------------------------------------------------------------
__global__ void proj_kernel(const float* __restrict__ x, int N, int Fin,
                            const float* __restrict__ W, const float* __restrict__ b,
                            float* __restrict__ h,
                            const float* __restrict__ att0, float* __restrict__ ao0,
                            const float* __restrict__ att1, float* __restrict__ ao1,
                            const float* __restrict__ att2, float* __restrict__ ao2,
                            const float* __restrict__ att3, float* __restrict__ ao3,
                            int relu_in)
{
    __shared__ float sW[64 * HID];
    __shared__ float sb[HID];
    __shared__ float satt[4][HID];
    int tid = threadIdx.x;
    for (int i = tid; i < Fin * HID; i += blockDim.x) sW[i] = W[i];
    if (tid < HID) {
        sb[tid]      = b[tid];
        satt[0][tid] = att0 ? att0[tid] : 0.f;
        satt[1][tid] = att1 ? att1[tid] : 0.f;
        satt[2][tid] = att2 ? att2[tid] : 0.f;
        satt[3][tid] = att3 ? att3[tid] : 0.f;
    }
    __syncthreads();
    int n = blockIdx.x * blockDim.x + tid;
    if (n >= N) return;

    float acc[HID];
#pragma unroll
    for (int c = 0; c < HID; c++) acc[c] = sb[c];
    const float* xr = x + (size_t)n * Fin;
    for (int k = 0; k < Fin; k++) {
        float xv = xr[k];
        if (relu_in) xv = fmaxf(xv, 0.f);
#pragma unroll
        for (int c = 0; c < HID; c++) acc[c] = fmaf(xv, sW[k * HID + c], acc[c]);
    }
    float4* hv = reinterpret_cast<float4*>(h + (size_t)n * HID);
#pragma unroll
    for (int j = 0; j < 8; j++)
        hv[j] = make_float4(acc[4*j], acc[4*j+1], acc[4*j+2], acc[4*j+3]);

    float al[4][4];
#pragma unroll
    for (int hh = 0; hh < 4; hh++) {
        float s0 = 0.f, s1 = 0.f, s2 = 0.f, s3 = 0.f;
#pragma unroll
        for (int d = 0; d < 8; d++) {
            float v = acc[hh * 8 + d];
            s0 = fmaf(v, satt[0][hh*8+d], s0);
            s1 = fmaf(v, satt[1][hh*8+d], s1);
            s2 = fmaf(v, satt[2][hh*8+d], s2);
            s3 = fmaf(v, satt[3][hh*8+d], s3);
        }
        al[0][hh] = s0; al[1][hh] = s1; al[2][hh] = s2; al[3][hh] = s3;
    }
    if (ao0) *reinterpret_cast<float4*>(ao0 + (size_t)n*4) = make_float4(al[0][0],al[0][1],al[0][2],al[0][3]);
    if (ao1) *reinterpret_cast<float4*>(ao1 + (size_t)n*4) = make_float4(al[1][0],al[1][1],al[1][2],al[1][3]);
    if (ao2) *reinterpret_cast<float4*>(ao2 + (size_t)n*4) = make_float4(al[2][0],al[2][1],al[2][2],al[2][3]);
    if (ao3) *reinterpret_cast<float4*>(ao3 + (size_t)n*4) = make_float4(al[3][0],al[3][1],al[3][2],al[3][3]);
}

// ---------------------------------------------------------------------------
// Single-pass CSR relation gather: warp per dst node, lane = channel.
// out[d] = sum_e(exp(leaky(as[s]+ad[d])) * h_src[s]) / (sum_e exp + 1e-16)
// ---------------------------------------------------------------------------
__global__ void relation_gather(const int* __restrict__ rs, const int* __restrict__ cnt,
                                const int* __restrict__ col,
                                const float* __restrict__ as, const float* __restrict__ ad,
                                const float* __restrict__ hsrc, float* __restrict__ out,
                                int Ndst)
{
    int w = (blockIdx.x * blockDim.x + threadIdx.x) >> 5;
    int lane = threadIdx.x & 31;
    if (w >= Ndst) return;
    int head = lane >> 3;
    float adv = ad[(size_t)w * 4 + head];
    int start = rs[w];
    int n = cnt[w];
    float acc = 0.f, ds = 0.f;
    if (n > 0) {
        int   s   = col[start];
        float asv = as[s * 4 + head];
        float v   = hsrc[(size_t)s * HID + lane];
        for (int j = 1; j < n; j++) {
            int   s2   = col[start + j];
            float asv2 = as[s2 * 4 + head];
            float v2   = hsrc[(size_t)s2 * HID + lane];
            float wgt = __expf(fminf(leaky(asv + adv), 70.f));
            acc = fmaf(v, wgt, acc);
            ds += wgt;
            asv = asv2; v = v2;
        }
        float wgt = __expf(fminf(leaky(asv + adv), 70.f));
        acc = fmaf(v, wgt, acc);
        ds += wgt;
    }
    out[(size_t)w * HID + lane] = acc / (ds + 1e-16f);
}

// ---------------------------------------------------------------------------
// Semantic attention
// ---------------------------------------------------------------------------
__global__ void sem_mean_kernel(const float* __restrict__ o1, const float* __restrict__ o2,
                                const float* __restrict__ kW, const float* __restrict__ kb,
                                float* __restrict__ sem, int N)
{
    __shared__ float sW[HID * HID];
    __shared__ float sb[HID];
    __shared__ float sacc[64];
    int tid = threadIdx.x;
    for (int i = tid; i < HID * HID; i += blockDim.x) sW[i] = kW[i];
    if (tid < HID) sb[tid] = kb[tid];
    if (tid < 64) sacc[tid] = 0.f;
    __syncthreads();

    int n = blockIdx.x * blockDim.x + tid;
    bool valid = (n < N);
#pragma unroll
    for (int r = 0; r < 2; r++) {
        const float* o = (r == 0) ? o1 : o2;
        float row[HID];
        if (valid) {
            const float4* rv = reinterpret_cast<const float4*>(o + (size_t)n * HID);
#pragma unroll
            for (int j = 0; j < 8; j++) {
                float4 v = rv[j];
                row[4*j+0] = fmaxf(v.x, 0.f); row[4*j+1] = fmaxf(v.y, 0.f);
                row[4*j+2] = fmaxf(v.z, 0.f); row[4*j+3] = fmaxf(v.w, 0.f);
            }
        } else {
#pragma unroll
            for (int j = 0; j < HID; j++) row[j] = 0.f;
        }
#pragma unroll
        for (int c = 0; c < HID; c++) {
            float acc = sb[c];
#pragma unroll
            for (int k = 0; k < HID; k++) acc = fmaf(row[k], sW[k * HID + c], acc);
            float v = valid ? tanhf(acc) : 0.f;
#pragma unroll
            for (int off = 16; off > 0; off >>= 1)
                v += __shfl_down_sync(0xFFFFFFFFu, v, off);
            if ((tid & 31) == 0) atomicAdd(&sacc[r * HID + c], v);
        }
    }
    __syncthreads();
    if (tid < 64) atomicAdd(&sem[tid], sacc[tid]);
}

__global__ void attn_kernel(const float* __restrict__ sem, const float* __restrict__ q,
                            float* __restrict__ attn, float invN)
{
    __shared__ float sc[2];
    int tid = threadIdx.x;
    float v = (sem[tid] * invN) * q[tid & 31];
#pragma unroll
    for (int off = 16; off > 0; off >>= 1)
        v += __shfl_down_sync(0xFFFFFFFFu, v, off);
    if ((tid & 31) == 0) sc[tid >> 5] = v;
    __syncthreads();
    if (tid == 0) {
        float m = fmaxf(sc[0], sc[1]);
        float e0 = __expf(sc[0] - m), e1 = __expf(sc[1] - m);
        float inv = 1.f / (e0 + e1);
        attn[0] = e0 * inv; attn[1] = e1 * inv;
    }
}

__global__ void combine_kernel(const float* __restrict__ o1, const float* __restrict__ o2,
                               const float* __restrict__ attn, float* __restrict__ A, int Ntot)
{
    int i = blockIdx.x * blockDim.x + threadIdx.x;
    if (i >= Ntot) return;
    float a0 = attn[0], a1 = attn[1];
    A[i] = a0 * fmaxf(o1[i], 0.f) + a1 * fmaxf(o2[i], 0.f);
}

__global__ void combine_final_kernel(const float* __restrict__ o1, const float* __restrict__ o2,
                                     const float* __restrict__ attn,
                                     const float* __restrict__ linW, const float* __restrict__ linb,
                                     float* __restrict__ out, int N)
{
    __shared__ float sw[64];
    __shared__ float sb2[2];
    int tid = threadIdx.x;
    if (tid < 64) sw[tid] = linW[tid];
    if (tid < 2)  sb2[tid] = linb[tid];
    __syncthreads();
    int n = blockIdx.x * blockDim.x + tid;
    if (n >= N) return;
    float a0 = attn[0], a1 = attn[1];
    float s0 = sb2[0], s1 = sb2[1];
    const float4* r1 = reinterpret_cast<const float4*>(o1 + (size_t)n * HID);
    const float4* r2 = reinterpret_cast<const float4*>(o2 + (size_t)n * HID);
#pragma unroll
    for (int j = 0; j < 8; j++) {
        float4 v1 = r1[j], v2 = r2[j];
        float c;
        c = a0*fmaxf(v1.x,0.f) + a1*fmaxf(v2.x,0.f); s0 = fmaf(c, sw[(4*j+0)*2+0], s0); s1 = fmaf(c, sw[(4*j+0)*2+1], s1);
        c = a0*fmaxf(v1.y,0.f) + a1*fmaxf(v2.y,0.f); s0 = fmaf(c, sw[(4*j+1)*2+0], s0); s1 = fmaf(c, sw[(4*j+1)*2+1], s1);
        c = a0*fmaxf(v1.z,0.f) + a1*fmaxf(v2.z,0.f); s0 = fmaf(c, sw[(4*j+2)*2+0], s0); s1 = fmaf(c, sw[(4*j+2)*2+1], s1);
        c = a0*fmaxf(v1.w,0.f) + a1*fmaxf(v2.w,0.f); s0 = fmaf(c, sw[(4*j+3)*2+0], s0); s1 = fmaf(c, sw[(4*j+3)*2+1], s1);
    }
    out[n * 2 + 0] = s0;
    out[n * 2 + 1] = s1;
}

// ---------------------------------------------------------------------------
// Host orchestration
// ---------------------------------------------------------------------------
static void build_csr(const int* src, const int* dst, int E, int N,
                      int* cnt, int* cur, int* rs, int* col, int* bsums)
{
    cudaMemsetAsync(cnt, 0, sizeof(int) * N);
    cudaMemsetAsync(cur, 0, sizeof(int) * N);
    hist_kernel<<<(E + TB - 1) / TB, TB>>>(dst, E, cnt);
    int nb = (N + SCAN_T - 1) / SCAN_T;
    scan_reduce_kernel<<<nb, SCAN_T>>>(cnt, N, bsums);
    scan_bsums_kernel<<<1, 512>>>(bsums, nb);
    scan_apply_kernel<<<nb, SCAN_T>>>(cnt, rs, bsums, N);
    fill_kernel<<<(E + TB - 1) / TB, TB>>>(src, dst, E, rs, cur, col);
}

static void launch_layer(const float* xa, const float* xt, int Fin, int relu_t,
                         const float* Wa, const float* ba, const float* Wt, const float* bt,
                         const float* attS, const float* attD,
                         const float* kW, const float* kb, const float* qv,
                         Scratch* S, bool with_tx,
                         const float* linW, const float* linb, float* out)
{
    int nba = (N_ADDR + TB - 1) / TB;
    int nbt = (N_TX   + TB - 1) / TB;

    proj_kernel<<<nba, TB>>>(xa, N_ADDR, Fin, Wa, ba, S->ha,
        with_tx ? attS + 0 : (const float*)nullptr, with_tx ? S->as_at : (float*)nullptr,
        attD + 32, S->ad_ta,
        attS + 64, S->as_aa,
        attD + 64, S->ad_aa, 0);
    proj_kernel<<<nbt, TB>>>(xt, N_TX, Fin, Wt, bt, S->ht,
        with_tx ? attD + 0 : (const float*)nullptr, with_tx ? S->ad_at : (float*)nullptr,
        attS + 32, S->as_ta,
        nullptr, nullptr, nullptr, nullptr, relu_t);

    cudaMemsetAsync(S->sem, 0, sizeof(float) * 64);

    int gb_tx = (N_TX   * 32 + TB - 1) / TB;
    int gb_a  = (N_ADDR * 32 + TB - 1) / TB;

    if (with_tx)
        relation_gather<<<gb_tx, TB>>>(S->rs_at, S->cnt_at, S->col_at,
                                       S->as_at, S->ad_at, S->ha, S->otx, N_TX);
    relation_gather<<<gb_a, TB>>>(S->rs_ta, S->cnt_ta, S->col_ta,
                                  S->as_ta, S->ad_ta, S->ht, S->oa1, N_ADDR);
    relation_gather<<<gb_a, TB>>>(S->rs_aa, S->cnt_aa, S->col_aa,
                                  S->as_aa, S->ad_aa, S->ha, S->oa2, N_ADDR);

    sem_mean_kernel<<<nba, TB>>>(S->oa1, S->oa2, kW, kb, S->sem, N_ADDR);
    attn_kernel<<<1, 64>>>(S->sem, qv, S->attn, 1.f / (float)N_ADDR);

    if (out) {
        combine_final_kernel<<<nba, TB>>>(S->oa1, S->oa2, S->attn, linW, linb, out, N_ADDR);
    } else {
        int nbc = (N_ADDR * HID + TB - 1) / TB;
        combine_kernel<<<nbc, TB>>>(S->oa1, S->oa2, S->attn, S->A, N_ADDR * HID);
    }
}

extern "C" void kernel_launch(void* const* d_in, const int* in_sizes, int n_in,
                              void* d_out, int out_size)
{
    const float* x_addr  = (const float*)d_in[0];
    const float* x_tx    = (const float*)d_in[1];
    const int*   eat_s   = (const int*)d_in[2];
    const int*   eat_d   = (const int*)d_in[3];
    const int*   eta_s   = (const int*)d_in[4];
    const int*   eta_d   = (const int*)d_in[5];
    const int*   eaa_s   = (const int*)d_in[6];
    const int*   eaa_d   = (const int*)d_in[7];
    const float* pW1     = (const float*)d_in[8];
    const float* pb1     = (const float*)d_in[9];
    const float* pW23    = (const float*)d_in[10];
    const float* pb23    = (const float*)d_in[11];
    const float* att_src = (const float*)d_in[12];
    const float* att_dst = (const float*)d_in[13];
    const float* kW      = (const float*)d_in[14];
    const float* kb      = (const float*)d_in[15];
    const float* q       = (const float*)d_in[16];
    const float* linW    = (const float*)d_in[17];
    const float* linb    = (const float*)d_in[18];
    float* out = (float*)d_out;

    Scratch* S = nullptr;
    cudaGetSymbolAddress((void**)&S, g_scr);

    // Build dst-CSR for each edge type (reused by all 3 layers)
    build_csr(eat_s, eat_d, E_AT, N_TX,   S->cnt_at, S->cur_at, S->rs_at, S->col_at, S->bsums);
    build_csr(eta_s, eta_d, E_TA, N_ADDR, S->cnt_ta, S->cur_ta, S->rs_ta, S->col_ta, S->bsums);
    build_csr(eaa_s, eaa_d, E_AA, N_ADDR, S->cnt_aa, S->cur_aa, S->rs_aa, S->col_aa, S->bsums);

    // Layer 1 (Fin=64)
    launch_layer(x_addr, x_tx, 64, 0,
                 pW1 + 0, pb1 + 0, pW1 + 64 * 32, pb1 + 32,
                 att_src + 0,  att_dst + 0,
                 kW + 0, kb + 0, q + 0,
                 S, true, nullptr, nullptr, nullptr);

    // Layer 2 (Fin=32)
    launch_layer(S->A, S->otx, 32, 1,
                 pW23 + 0 * 1024, pb23 + 0, pW23 + 1 * 1024, pb23 + 32,
                 att_src + 96, att_dst + 96,
                 kW + 1024, kb + 32, q + 32,
                 S, true, nullptr, nullptr, nullptr);

    // Layer 3: tx outputs dead -> skip at relation; fuse final linear
    launch_layer(S->A, S->otx, 32, 1,
                 pW23 + 2 * 1024, pb23 + 64, pW23 + 3 * 1024, pb23 + 96,
                 att_src + 192, att_dst + 192,
                 kW + 2048, kb + 64, q + 64,
                 S, false, linW, linb, out);

    (void)in_sizes; (void)n_in; (void)out_size;
}

// round 4
// speedup vs baseline: 1.6672x; 1.6672x over previous
#include <cuda_runtime.h>
#include <math.h>

#define N_ADDR 150000
#define N_TX   200000
#define HID    32
#define E_TA   1000000
#define E_AA   500000
#define E_AT   1000000
#define E_TOT  2500000
#define NDST   500000      // concatenated dst space: [ta addr | aa addr | at tx]
#define SLOPE  0.2f
#define TB     256
#define SCAN_T 1024

// ---------------------------------------------------------------------------
// Scratch (device global — no runtime allocation)
// ---------------------------------------------------------------------------
struct __align__(128) Scratch {
    float ha [N_ADDR * HID];
    float ht [N_TX   * HID];
    float otx[N_TX   * HID];
    float oa1[N_ADDR * HID];
    float oa2[N_ADDR * HID];
    float as_at[N_ADDR * 4];
    float ad_at[N_TX   * 4];
    float as_ta[N_TX   * 4];
    float ad_ta[N_ADDR * 4];
    float as_aa[N_ADDR * 4];
    float ad_aa[N_ADDR * 4];
    float sem[64];
    float attn[2];
    int cnt[NDST];
    int cur[NDST];
    int rs [NDST];
    int col[E_TOT];
    int bsums[512];
};
__device__ Scratch g_scr;

__device__ __forceinline__ float leaky(float v) { return v >= 0.f ? v : SLOPE * v; }
__device__ __forceinline__ float tanh_approx(float x) {
    float r; asm("tanh.approx.f32 %0, %1;" : "=f"(r) : "f"(x)); return r;
}

// ---------------------------------------------------------------------------
// CSR build (one concatenated CSR for all 3 relations)
// edge order in concat space: [ta (1M) | aa (0.5M) | at (1M)]
// dst space:                  [ta addr (150K) | aa addr (150K) | at tx (200K)]
// ---------------------------------------------------------------------------
__device__ __forceinline__ int edge_gdst(int e, const int* ta_d, const int* aa_d, const int* at_d)
{
    if (e < E_TA)         return ta_d[e];
    if (e < E_TA + E_AA)  return N_ADDR + aa_d[e - E_TA];
    return 2 * N_ADDR + at_d[e - E_TA - E_AA];
}

__global__ void hist_fused(const int* __restrict__ ta_d, const int* __restrict__ aa_d,
                           const int* __restrict__ at_d, int* __restrict__ cnt)
{
    int e = blockIdx.x * blockDim.x + threadIdx.x;
    if (e >= E_TOT) return;
    atomicAdd(&cnt[edge_gdst(e, ta_d, aa_d, at_d)], 1);
}

__global__ void scan_reduce_kernel(const int* __restrict__ cnt, int n, int* __restrict__ bsums)
{
    __shared__ int sd[SCAN_T];
    int tid = threadIdx.x;
    int i = blockIdx.x * SCAN_T + tid;
    sd[tid] = (i < n) ? cnt[i] : 0;
    __syncthreads();
#pragma unroll
    for (int off = SCAN_T / 2; off > 0; off >>= 1) {
        if (tid < off) sd[tid] += sd[tid + off];
        __syncthreads();
    }
    if (tid == 0) bsums[blockIdx.x] = sd[0];
}

__global__ void scan_bsums_kernel(int* __restrict__ bsums, int nb)
{
    __shared__ int sd[512];
    int tid = threadIdx.x;
    sd[tid] = (tid < nb) ? bsums[tid] : 0;
    __syncthreads();
    if (tid == 0) {
        int run = 0;
        for (int i = 0; i < nb; i++) { int t = sd[i]; sd[i] = run; run += t; }
    }
    __syncthreads();
    if (tid < nb) bsums[tid] = sd[tid];
}

__global__ void scan_apply_kernel(const int* __restrict__ cnt, int* __restrict__ rs,
                                  const int* __restrict__ bsums, int n)
{
    __shared__ int sd[SCAN_T];
    int tid = threadIdx.x;
    int i = blockIdx.x * SCAN_T + tid;
    int v = (i < n) ? cnt[i] : 0;
    sd[tid] = v;
    __syncthreads();
#pragma unroll
    for (int off = 1; off < SCAN_T; off <<= 1) {
        int t = (tid >= off) ? sd[tid - off] : 0;
        __syncthreads();
        sd[tid] += t;
        __syncthreads();
    }
    if (i < n) rs[i] = sd[tid] - v + bsums[blockIdx.x];
}

__global__ void fill_fused(const int* __restrict__ ta_s, const int* __restrict__ ta_d,
                           const int* __restrict__ aa_s, const int* __restrict__ aa_d,
                           const int* __restrict__ at_s, const int* __restrict__ at_d,
                           const int* __restrict__ rs, int* __restrict__ cur,
                           int* __restrict__ col)
{
    int e = blockIdx.x * blockDim.x + threadIdx.x;
    if (e >= E_TOT) return;
    int g, s;
    if (e < E_TA)              { g = ta_d[e];                        s = ta_s[e]; }
    else if (e < E_TA + E_AA)  { g = N_ADDR + aa_d[e - E_TA];        s = aa_s[e - E_TA]; }
    else                       { g = 2*N_ADDR + at_d[e - E_TA - E_AA]; s = at_s[e - E_TA - E_AA]; }
    int pos = rs[g] + atomicAdd(&cur[g], 1);
    col[pos] = s;
}

// ---------------------------------------------------------------------------
// Fused projection for both node types; fused semantic-combine input for L2/L3.
// Blocks [0, nba) -> addr nodes; [nba, nba+nbt) -> tx nodes.
// ---------------------------------------------------------------------------
__global__ void proj_fused(int layer1, int Fin, int nba_blocks,
                           const float* __restrict__ xa,        // layer1: raw addr input
                           const float* __restrict__ xt,        // layer1: raw tx / else otx
                           const float* __restrict__ o1, const float* __restrict__ o2,
                           const float* __restrict__ attn,
                           const float* __restrict__ Wa, const float* __restrict__ ba,
                           const float* __restrict__ Wt, const float* __restrict__ bt,
                           float* __restrict__ ha, float* __restrict__ ht,
                           const float* __restrict__ attS, const float* __restrict__ attD,
                           float* __restrict__ as_at, float* __restrict__ ad_ta,
                           float* __restrict__ as_aa, float* __restrict__ ad_aa,
                           float* __restrict__ ad_at, float* __restrict__ as_ta)
{
    __shared__ float sW[64 * HID];
    __shared__ float sb[HID];
    __shared__ float satt[4][HID];
    int tid = threadIdx.x;
    bool is_addr = (blockIdx.x < (unsigned)nba_blocks);
    const float* W = is_addr ? Wa : Wt;
    const float* b = is_addr ? ba : bt;
    for (int i = tid; i < Fin * HID; i += blockDim.x) sW[i] = W[i];
    if (tid < HID) {
        sb[tid] = b[tid];
        if (is_addr) {
            satt[0][tid] = attS[tid];            // att_src[at]
            satt[1][tid] = attD[32 + tid];       // att_dst[ta]
            satt[2][tid] = attS[64 + tid];       // att_src[aa]
            satt[3][tid] = attD[64 + tid];       // att_dst[aa]
        } else {
            satt[0][tid] = attD[tid];            // att_dst[at]
            satt[1][tid] = attS[32 + tid];       // att_src[ta]
            satt[2][tid] = 0.f;
            satt[3][tid] = 0.f;
        }
    }
    __syncthreads();

    int blk = is_addr ? blockIdx.x : (blockIdx.x - nba_blocks);
    int N   = is_addr ? N_ADDR : N_TX;
    int n   = blk * blockDim.x + tid;
    if (n >= N) return;

    float a0 = 0.f, a1 = 0.f;
    if (!layer1 && is_addr) { a0 = attn[0]; a1 = attn[1]; }

    float acc[HID];
#pragma unroll
    for (int c = 0; c < HID; c++) acc[c] = sb[c];

    if (is_addr) {
        if (layer1) {
            const float* xr = xa + (size_t)n * Fin;
            for (int k = 0; k < Fin; k++) {
                float xv = xr[k];
#pragma unroll
                for (int c = 0; c < HID; c++) acc[c] = fmaf(xv, sW[k * HID + c], acc[c]);
            }
        } else {
            const float* r1 = o1 + (size_t)n * HID;
            const float* r2 = o2 + (size_t)n * HID;
#pragma unroll
            for (int k = 0; k < HID; k++) {
                float xv = a0 * fmaxf(r1[k], 0.f) + a1 * fmaxf(r2[k], 0.f);
#pragma unroll
                for (int c = 0; c < HID; c++) acc[c] = fmaf(xv, sW[k * HID + c], acc[c]);
            }
        }
    } else {
        const float* xr = xt + (size_t)n * Fin;
        for (int k = 0; k < Fin; k++) {
            float xv = xr[k];
            if (!layer1) xv = fmaxf(xv, 0.f);
#pragma unroll
            for (int c = 0; c < HID; c++) acc[c] = fmaf(xv, sW[k * HID + c], acc[c]);
        }
    }

    float* h = is_addr ? ha : ht;
    float4* hv = reinterpret_cast<float4*>(h + (size_t)n * HID);
#pragma unroll
    for (int j = 0; j < 8; j++)
        hv[j] = make_float4(acc[4*j], acc[4*j+1], acc[4*j+2], acc[4*j+3]);

    float al[4][4];
#pragma unroll
    for (int hh = 0; hh < 4; hh++) {
        float s0 = 0.f, s1 = 0.f, s2 = 0.f, s3 = 0.f;
#pragma unroll
        for (int d = 0; d < 8; d++) {
            float v = acc[hh * 8 + d];
            s0 = fmaf(v, satt[0][hh*8+d], s0);
            s1 = fmaf(v, satt[1][hh*8+d], s1);
            s2 = fmaf(v, satt[2][hh*8+d], s2);
            s3 = fmaf(v, satt[3][hh*8+d], s3);
        }
        al[0][hh] = s0; al[1][hh] = s1; al[2][hh] = s2; al[3][hh] = s3;
    }
    if (is_addr) {
        *reinterpret_cast<float4*>(as_at + (size_t)n*4) = make_float4(al[0][0],al[0][1],al[0][2],al[0][3]);
        *reinterpret_cast<float4*>(ad_ta + (size_t)n*4) = make_float4(al[1][0],al[1][1],al[1][2],al[1][3]);
        *reinterpret_cast<float4*>(as_aa + (size_t)n*4) = make_float4(al[2][0],al[2][1],al[2][2],al[2][3]);
        *reinterpret_cast<float4*>(ad_aa + (size_t)n*4) = make_float4(al[3][0],al[3][1],al[3][2],al[3][3]);
    } else {
        *reinterpret_cast<float4*>(ad_at + (size_t)n*4) = make_float4(al[0][0],al[0][1],al[0][2],al[0][3]);
        *reinterpret_cast<float4*>(as_ta + (size_t)n*4) = make_float4(al[1][0],al[1][1],al[1][2],al[1][3]);
    }
}

// ---------------------------------------------------------------------------
// Fused relation gather: warp per dst node across all relations; lane=channel.
// Warp ranges: [0,150K)=ta->oa1, [150K,300K)=aa->oa2, [300K,500K)=at->otx.
// 4-way batched inner loop for MLP.
// ---------------------------------------------------------------------------
__global__ void gather_fused(const int* __restrict__ rs, const int* __restrict__ col,
                             const float* __restrict__ as_ta, const float* __restrict__ ad_ta,
                             const float* __restrict__ ht,   float* __restrict__ oa1,
                             const float* __restrict__ as_aa, const float* __restrict__ ad_aa,
                             const float* __restrict__ ha,   float* __restrict__ oa2,
                             const float* __restrict__ as_at, const float* __restrict__ ad_at,
                             float* __restrict__ otx, int nwarps)
{
    int w = (blockIdx.x * blockDim.x + threadIdx.x) >> 5;
    if (w >= nwarps) return;
    int lane = threadIdx.x & 31;
    int head = lane >> 3;

    const float *as, *ad, *hs;
    float* out;
    int d;
    if (w < N_ADDR)            { as = as_ta; ad = ad_ta; hs = ht; out = oa1; d = w; }
    else if (w < 2 * N_ADDR)   { as = as_aa; ad = ad_aa; hs = ha; out = oa2; d = w - N_ADDR; }
    else                       { as = as_at; ad = ad_at; hs = ha; out = otx; d = w - 2 * N_ADDR; }

    int start = rs[w];
    int end   = (w + 1 < NDST) ? rs[w + 1] : E_TOT;
    float adv = ad[(size_t)d * 4 + head];

    float acc = 0.f, ds = 0.f;
    int j = start;
    for (; j + 4 <= end; j += 4) {
        int s0 = col[j], s1 = col[j+1], s2 = col[j+2], s3 = col[j+3];
        float b0 = as[s0 * 4 + head];
        float b1 = as[s1 * 4 + head];
        float b2 = as[s2 * 4 + head];
        float b3 = as[s3 * 4 + head];
        float v0 = hs[(size_t)s0 * HID + lane];
        float v1 = hs[(size_t)s1 * HID + lane];
        float v2 = hs[(size_t)s2 * HID + lane];
        float v3 = hs[(size_t)s3 * HID + lane];
        float w0 = __expf(fminf(leaky(b0 + adv), 70.f));
        float w1 = __expf(fminf(leaky(b1 + adv), 70.f));
        float w2 = __expf(fminf(leaky(b2 + adv), 70.f));
        float w3 = __expf(fminf(leaky(b3 + adv), 70.f));
        acc = fmaf(v0, w0, acc); acc = fmaf(v1, w1, acc);
        acc = fmaf(v2, w2, acc); acc = fmaf(v3, w3, acc);
        ds += (w0 + w1) + (w2 + w3);
    }
    for (; j < end; j++) {
        int s = col[j];
        float wg = __expf(fminf(leaky(as[s * 4 + head] + adv), 70.f));
        acc = fmaf(hs[(size_t)s * HID + lane], wg, acc);
        ds += wg;
    }
    out[(size_t)d * HID + lane] = acc / (ds + 1e-16f);
}

// ---------------------------------------------------------------------------
// Semantic attention
// ---------------------------------------------------------------------------
__global__ void sem_mean_kernel(const float* __restrict__ o1, const float* __restrict__ o2,
                                const float* __restrict__ kW, const float* __restrict__ kb,
                                float* __restrict__ sem, int N)
{
    __shared__ float sW[HID * HID];
    __shared__ float sb[HID];
    __shared__ float sacc[64];
    int tid = threadIdx.x;
    for (int i = tid; i < HID * HID; i += blockDim.x) sW[i] = kW[i];
    if (tid < HID) sb[tid] = kb[tid];
    if (tid < 64) sacc[tid] = 0.f;
    __syncthreads();

    int n = blockIdx.x * blockDim.x + tid;
    bool valid = (n < N);
#pragma unroll
    for (int r = 0; r < 2; r++) {
        const float* o = (r == 0) ? o1 : o2;
        float row[HID];
        if (valid) {
            const float4* rv = reinterpret_cast<const float4*>(o + (size_t)n * HID);
#pragma unroll
            for (int j = 0; j < 8; j++) {
                float4 v = rv[j];
                row[4*j+0] = fmaxf(v.x, 0.f); row[4*j+1] = fmaxf(v.y, 0.f);
                row[4*j+2] = fmaxf(v.z, 0.f); row[4*j+3] = fmaxf(v.w, 0.f);
            }
        } else {
#pragma unroll
            for (int j = 0; j < HID; j++) row[j] = 0.f;
        }
#pragma unroll
        for (int c = 0; c < HID; c++) {
            float acc = sb[c];
#pragma unroll
            for (int k = 0; k < HID; k++) acc = fmaf(row[k], sW[k * HID + c], acc);
            float v = valid ? tanh_approx(acc) : 0.f;
#pragma unroll
            for (int off = 16; off > 0; off >>= 1)
                v += __shfl_down_sync(0xFFFFFFFFu, v, off);
            if ((tid & 31) == 0) atomicAdd(&sacc[r * HID + c], v);
        }
    }
    __syncthreads();
    if (tid < 64) atomicAdd(&sem[tid], sacc[tid]);
}

__global__ void attn_kernel(const float* __restrict__ sem, const float* __restrict__ q,
                            float* __restrict__ attn, float invN)
{
    __shared__ float sc[2];
    int tid = threadIdx.x;
    float v = (sem[tid] * invN) * q[tid & 31];
#pragma unroll
    for (int off = 16; off > 0; off >>= 1)
        v += __shfl_down_sync(0xFFFFFFFFu, v, off);
    if ((tid & 31) == 0) sc[tid >> 5] = v;
    __syncthreads();
    if (tid == 0) {
        float m = fmaxf(sc[0], sc[1]);
        float e0 = __expf(sc[0] - m), e1 = __expf(sc[1] - m);
        float inv = 1.f / (e0 + e1);
        attn[0] = e0 * inv; attn[1] = e1 * inv;
    }
}

__global__ void combine_final_kernel(const float* __restrict__ o1, const float* __restrict__ o2,
                                     const float* __restrict__ attn,
                                     const float* __restrict__ linW, const float* __restrict__ linb,
                                     float* __restrict__ out, int N)
{
    __shared__ float sw[64];
    __shared__ float sb2[2];
    int tid = threadIdx.x;
    if (tid < 64) sw[tid] = linW[tid];
    if (tid < 2)  sb2[tid] = linb[tid];
    __syncthreads();
    int n = blockIdx.x * blockDim.x + tid;
    if (n >= N) return;
    float a0 = attn[0], a1 = attn[1];
    float s0 = sb2[0], s1 = sb2[1];
    const float4* r1 = reinterpret_cast<const float4*>(o1 + (size_t)n * HID);
    const float4* r2 = reinterpret_cast<const float4*>(o2 + (size_t)n * HID);
#pragma unroll
    for (int j = 0; j < 8; j++) {
        float4 v1 = r1[j], v2 = r2[j];
        float c;
        c = a0*fmaxf(v1.x,0.f) + a1*fmaxf(v2.x,0.f); s0 = fmaf(c, sw[(4*j+0)*2+0], s0); s1 = fmaf(c, sw[(4*j+0)*2+1], s1);
        c = a0*fmaxf(v1.y,0.f) + a1*fmaxf(v2.y,0.f); s0 = fmaf(c, sw[(4*j+1)*2+0], s0); s1 = fmaf(c, sw[(4*j+1)*2+1], s1);
        c = a0*fmaxf(v1.z,0.f) + a1*fmaxf(v2.z,0.f); s0 = fmaf(c, sw[(4*j+2)*2+0], s0); s1 = fmaf(c, sw[(4*j+2)*2+1], s1);
        c = a0*fmaxf(v1.w,0.f) + a1*fmaxf(v2.w,0.f); s0 = fmaf(c, sw[(4*j+3)*2+0], s0); s1 = fmaf(c, sw[(4*j+3)*2+1], s1);
    }
    out[n * 2 + 0] = s0;
    out[n * 2 + 1] = s1;
}

// ---------------------------------------------------------------------------
// Host orchestration
// ---------------------------------------------------------------------------
static void launch_layer(int layer1, int Fin,
                         const float* xa, const float* xt_or_otx,
                         const float* Wa, const float* ba, const float* Wt, const float* bt,
                         const float* attS, const float* attD,
                         const float* kW, const float* kb, const float* qv,
                         Scratch* S, bool with_tx,
                         const float* linW, const float* linb, float* out)
{
    int nba = (N_ADDR + TB - 1) / TB;
    int nbt = (N_TX   + TB - 1) / TB;

    proj_fused<<<nba + nbt, TB>>>(layer1, Fin, nba,
        xa, xt_or_otx, S->oa1, S->oa2, S->attn,
        Wa, ba, Wt, bt, S->ha, S->ht, attS, attD,
        S->as_at, S->ad_ta, S->as_aa, S->ad_aa, S->ad_at, S->as_ta);

    cudaMemsetAsync(S->sem, 0, sizeof(float) * 64);

    int nwarps = with_tx ? NDST : 2 * N_ADDR;
    int gblocks = (nwarps * 32 + TB - 1) / TB;
    gather_fused<<<gblocks, TB>>>(S->rs, S->col,
        S->as_ta, S->ad_ta, S->ht, S->oa1,
        S->as_aa, S->ad_aa, S->ha, S->oa2,
        S->as_at, S->ad_at, S->otx, nwarps);

    sem_mean_kernel<<<nba, TB>>>(S->oa1, S->oa2, kW, kb, S->sem, N_ADDR);
    attn_kernel<<<1, 64>>>(S->sem, qv, S->attn, 1.f / (float)N_ADDR);

    if (out)
        combine_final_kernel<<<nba, TB>>>(S->oa1, S->oa2, S->attn, linW, linb, out, N_ADDR);
}

extern "C" void kernel_launch(void* const* d_in, const int* in_sizes, int n_in,
                              void* d_out, int out_size)
{
    const float* x_addr  = (const float*)d_in[0];
    const float* x_tx    = (const float*)d_in[1];
    const int*   eat_s   = (const int*)d_in[2];
    const int*   eat_d   = (const int*)d_in[3];
    const int*   eta_s   = (const int*)d_in[4];
    const int*   eta_d   = (const int*)d_in[5];
    const int*   eaa_s   = (const int*)d_in[6];
    const int*   eaa_d   = (const int*)d_in[7];
    const float* pW1     = (const float*)d_in[8];
    const float* pb1     = (const float*)d_in[9];
    const float* pW23    = (const float*)d_in[10];
    const float* pb23    = (const float*)d_in[11];
    const float* att_src = (const float*)d_in[12];
    const float* att_dst = (const float*)d_in[13];
    const float* kW      = (const float*)d_in[14];
    const float* kb      = (const float*)d_in[15];
    const float* q       = (const float*)d_in[16];
    const float* linW    = (const float*)d_in[17];
    const float* linb    = (const float*)d_in[18];
    float* out = (float*)d_out;

    Scratch* S = nullptr;
    cudaGetSymbolAddress((void**)&S, g_scr);

    // ---- Concatenated CSR build (7 launches) ----
    cudaMemsetAsync(S->cnt, 0, sizeof(int) * NDST);
    cudaMemsetAsync(S->cur, 0, sizeof(int) * NDST);
    hist_fused<<<(E_TOT + TB - 1) / TB, TB>>>(eta_d, eaa_d, eat_d, S->cnt);
    int nb = (NDST + SCAN_T - 1) / SCAN_T;   // 489
    scan_reduce_kernel<<<nb, SCAN_T>>>(S->cnt, NDST, S->bsums);
    scan_bsums_kernel<<<1, 512>>>(S->bsums, nb);
    scan_apply_kernel<<<nb, SCAN_T>>>(S->cnt, S->rs, S->bsums, NDST);
    fill_fused<<<(E_TOT + TB - 1) / TB, TB>>>(eta_s, eta_d, eaa_s, eaa_d, eat_s, eat_d,
                                              S->rs, S->cur, S->col);

    // ---- Layer 1 (Fin=64, raw inputs) ----
    launch_layer(1, 64, x_addr, x_tx,
                 pW1 + 0, pb1 + 0, pW1 + 64 * 32, pb1 + 32,
                 att_src + 0,  att_dst + 0,
                 kW + 0, kb + 0, q + 0,
                 S, true, nullptr, nullptr, nullptr);

    // ---- Layer 2 (Fin=32, addr = combine(oa1,oa2,attn), tx = relu(otx)) ----
    launch_layer(0, 32, nullptr, S->otx,
                 pW23 + 0 * 1024, pb23 + 0, pW23 + 1 * 1024, pb23 + 32,
                 att_src + 96, att_dst + 96,
                 kW + 1024, kb + 32, q + 32,
                 S, true, nullptr, nullptr, nullptr);

    // ---- Layer 3 (tx dead: skip at relation; fuse final linear) ----
    launch_layer(0, 32, nullptr, S->otx,
                 pW23 + 2 * 1024, pb23 + 64, pW23 + 3 * 1024, pb23 + 96,
                 att_src + 192, att_dst + 192,
                 kW + 2048, kb + 64, q + 64,
                 S, false, linW, linb, out);

    (void)in_sizes; (void)n_in; (void)out_size;
}